// round 9
// baseline (speedup 1.0000x reference)
#include <cuda_runtime.h>
#include <math.h>

#define LOG8 2.0794415416798357f
#define JTILE 1024    // j-elements per block (8 warps x 128)
#define ITERS 16      // i-rows per block
#define WARP_J 128    // j-elements per warp

// Per-warp staging buffer: [dxyz 1536B][bkt 512B][dsc 512B][msk 512B] = 3072B
#define WBUF_F (WARP_J * 6)            // floats per warp buffer (768)
#define TOTAL_SMEM_F (8 * 2 * WBUF_F)  // 8 warps x 2 phases = 48 KB

__device__ __forceinline__ float bucket_base(float d) {
    float x  = d * 2.0f;              // d / RES, exact
    float ax = fabsf(x);
    float r;
    if (ax <= 2.0f) {
        r = rintf(x);                 // jnp.round = half-to-even
    } else {
        float lr  = __fdiv_rn(logf(__fmul_rn(ax, 0.5f)), LOG8);
        float sup = fminf(rintf(__fsub_rn(2.0f, __fmul_rn(6.0f, lr))), 8.0f);
        r = (x > 0.0f) ? sup : -sup;
    }
    return 8.0f + r;
}

__device__ __forceinline__ unsigned smem_u32(const void* p) {
    return (unsigned)__cvta_generic_to_shared(p);
}

__global__ __launch_bounds__(256)
void pair_kernel(const float* __restrict__ xyz, const int* __restrict__ grid,
                 float* __restrict__ out, int N) {
    __shared__ float sbuf[TOTAL_SMEM_F];

    const int t     = threadIdx.x;
    const int w     = t >> 5;
    const int lane  = t & 31;
    const int jbase = blockIdx.x * JTILE + w * WARP_J;   // warp's j slice
    const int i0    = blockIdx.y * ITERS;
    const int j0    = jbase + lane * 4;

    // ---- pack this warp's 4 j-points into registers (once per block) ----
    float qjx[4], qjy[4], qjz[4];
    int w1j[4], w2j[4], blj[4];
#pragma unroll
    for (int p = 0; p < 4; p++) {
        const int j = j0 + p;
        qjx[p] = __ldg(xyz + (size_t)j * 3 + 0);
        qjy[p] = __ldg(xyz + (size_t)j * 3 + 1);
        qjz[p] = __ldg(xyz + (size_t)j * 3 + 2);
        const int b  = __ldg(grid + (size_t)j * 5 + 0);
        const int bl = __ldg(grid + (size_t)j * 5 + 1);
        const int c0 = __ldg(grid + (size_t)j * 5 + 2);
        const int c1 = __ldg(grid + (size_t)j * 5 + 3);
        const int c2 = __ldg(grid + (size_t)j * 5 + 4);
        const int cx = (int)ceilf(__fdiv_rn(qjx[p], 3.0f));
        const int cy = (int)ceilf(__fdiv_rn(qjy[p], 3.0f));
        w1j[p] = (bl << 24) | (c2 << 16) | (c1 << 8) | c0;
        w2j[p] = (b << 16) | (cy << 8) | cx;
        blj[p] = bl;
    }

    const size_t NN = (size_t)N * (size_t)N;

    for (int k = 0; k < ITERS; k++) {
        const int i = i0 + k;
        float* sb = &sbuf[(w * 2 + (k & 1)) * WBUF_F];

        // ---- per-i data (broadcast loads, L1-resident) ----
        const float xi = __ldg(xyz + (size_t)i * 3 + 0);
        const float yi = __ldg(xyz + (size_t)i * 3 + 1);
        const float zi = __ldg(xyz + (size_t)i * 3 + 2);
        const int bi   = __ldg(grid + (size_t)i * 5 + 0);
        const int bli  = __ldg(grid + (size_t)i * 5 + 1);
        const int ci0  = __ldg(grid + (size_t)i * 5 + 2);
        const int ci1  = __ldg(grid + (size_t)i * 5 + 3);
        const int ci2  = __ldg(grid + (size_t)i * 5 + 4);
        const int cxi  = (int)ceilf(__fdiv_rn(xi, 3.0f));
        const int cyi  = (int)ceilf(__fdiv_rn(yi, 3.0f));
        const int w1i  = (bli << 24) | (ci2 << 16) | (ci1 << 8) | ci0;
        const int w2i  = (bi << 16) | (cyi << 8) | cxi;
        const int sci  = bli >> 1;

        float dxv[12];
        float bkt[4], dsc[4], msk[4];

#pragma unroll
        for (int p = 0; p < 4; p++) {
            const float dx = xi - qjx[p];
            const float dy = yi - qjy[p];
            const float dz = zi - qjz[p];

            const unsigned d1 = __vabsdiffu4(w1i, w1j[p]);  // [c0d,c1d,c2d,bld]
            const unsigned d2 = __vabsdiffu4(w2i, w2j[p]);  // [cxd,cyd,bd,0]

            bool m = ((d2 & 0x00FF0000u) == 0u) && (bli <= blj[p]);
            if (m) {
                const bool fk = (d1 & 0xFFFEFEFEu) == 0u;
                if (!fk) {
                    const bool kc = (d2 & 0x0000FEFEu) == 0u;
                    const float r2 = __fadd_rn(__fadd_rn(__fmul_rn(dx, dx),
                                                         __fmul_rn(dy, dy)),
                                               __fmul_rn(dz, dz));
                    m = kc && (r2 <= 9.0f);
                }
            }

            if (m) {
                dxv[p * 3 + 0] = dx;
                dxv[p * 3 + 1] = dy;
                dxv[p * 3 + 2] = dz;
                bkt[p] = __fadd_rn(__fadd_rn(__fmul_rn(289.0f, bucket_base(dx)),
                                             __fmul_rn(17.0f, bucket_base(dy))),
                                   bucket_base(dz));
                dsc[p] = (float)((blj[p] >> 1) - sci);
                msk[p] = 1.0f;
            } else {
                dxv[p * 3 + 0] = 0.0f; dxv[p * 3 + 1] = 0.0f; dxv[p * 3 + 2] = 0.0f;
                bkt[p] = 0.0f; dsc[p] = 0.0f; msk[p] = 0.0f;
            }
        }

        // ---- ensure TMA from iter k-2 has finished reading this buffer ----
        if (k >= 2) {
            if (lane == 0)
                asm volatile("cp.async.bulk.wait_group.read 1;" ::: "memory");
            __syncwarp();
        }

        // ---- stage to warp-private SMEM (layout mirrors global slices) ----
        float4* sdx = reinterpret_cast<float4*>(&sb[lane * 12]);
        sdx[0] = make_float4(dxv[0], dxv[1], dxv[2],  dxv[3]);
        sdx[1] = make_float4(dxv[4], dxv[5], dxv[6],  dxv[7]);
        sdx[2] = make_float4(dxv[8], dxv[9], dxv[10], dxv[11]);
        *reinterpret_cast<float4*>(&sb[3 * WARP_J + lane * 4]) =
            make_float4(bkt[0], bkt[1], bkt[2], bkt[3]);
        *reinterpret_cast<float4*>(&sb[4 * WARP_J + lane * 4]) =
            make_float4(dsc[0], dsc[1], dsc[2], dsc[3]);
        *reinterpret_cast<float4*>(&sb[5 * WARP_J + lane * 4]) =
            make_float4(msk[0], msk[1], msk[2], msk[3]);

        __syncwarp();

        // ---- elected lane drains this warp's slice via bulk async stores ----
        if (lane == 0) {
            asm volatile("fence.proxy.async.shared::cta;" ::: "memory");

            const size_t row = (size_t)i * N + (size_t)jbase;
            float* g_dx = out + row * 3;
            float* g_bk = out + 3 * NN + row;
            float* g_ds = out + 4 * NN + row;
            float* g_mk = out + 5 * NN + row;

            const unsigned bytes1 = WARP_J * 4u;    // 512 B
            const unsigned bytes3 = bytes1 * 3u;    // 1536 B

            asm volatile("cp.async.bulk.global.shared::cta.bulk_group [%0], [%1], %2;"
                         :: "l"(g_dx), "r"(smem_u32(&sb[0])), "r"(bytes3) : "memory");
            asm volatile("cp.async.bulk.global.shared::cta.bulk_group [%0], [%1], %2;"
                         :: "l"(g_bk), "r"(smem_u32(&sb[3 * WARP_J])), "r"(bytes1) : "memory");
            asm volatile("cp.async.bulk.global.shared::cta.bulk_group [%0], [%1], %2;"
                         :: "l"(g_ds), "r"(smem_u32(&sb[4 * WARP_J])), "r"(bytes1) : "memory");
            asm volatile("cp.async.bulk.global.shared::cta.bulk_group [%0], [%1], %2;"
                         :: "l"(g_mk), "r"(smem_u32(&sb[5 * WARP_J])), "r"(bytes1) : "memory");
            asm volatile("cp.async.bulk.commit_group;" ::: "memory");
        }
    }

    // ---- final drain: all this warp's groups complete before block exit ----
    if (lane == 0) {
        asm volatile("cp.async.bulk.wait_group 0;" ::: "memory");
    }
    __syncwarp();
}

extern "C" void kernel_launch(void* const* d_in, const int* in_sizes, int n_in,
                              void* d_out, int out_size) {
    const float* xyz  = (const float*)d_in[0];   // [N,3] f32
    const int*   grid = (const int*)d_in[1];     // [N,5] i32
    float* out = (float*)d_out;

    const int N = in_sizes[0] / 3;               // 3072

    dim3 block(256, 1, 1);
    dim3 gridDim(N / JTILE, N / ITERS, 1);
    pair_kernel<<<gridDim, block>>>(xyz, grid, out, N);
}

// round 10
// speedup vs baseline: 1.1004x; 1.1004x over previous
#include <cuda_runtime.h>
#include <math.h>

#define LOG8 2.0794415416798357f
#define JTILE 1024   // j-elements per block (256 threads x 4)
#define ITERS 16     // i-rows per block

// SMEM tile layout (floats): [dxyz: 3*JTILE][bkt: JTILE][dsc: JTILE][msk: JTILE]
#define TILE_F (6 * JTILE)

__device__ __forceinline__ float bucket_base(float d) {
    float x  = d * 2.0f;              // d / RES, exact
    float ax = fabsf(x);
    float r;
    if (ax <= 2.0f) {
        r = rintf(x);                 // jnp.round = half-to-even
    } else {
        float lr  = __fdiv_rn(logf(__fmul_rn(ax, 0.5f)), LOG8);
        float sup = fminf(rintf(__fsub_rn(2.0f, __fmul_rn(6.0f, lr))), 8.0f);
        r = (x > 0.0f) ? sup : -sup;
    }
    return 8.0f + r;
}

__device__ __forceinline__ unsigned smem_u32(const void* p) {
    return (unsigned)__cvta_generic_to_shared(p);
}

__global__ __launch_bounds__(256)
void pair_kernel(const float* __restrict__ xyz, const int* __restrict__ grid,
                 float* __restrict__ out, int N) {
    __shared__ float  sbuf[2][TILE_F];    // 2 x 24 KB staging
    __shared__ float4 s_ipt[ITERS];       // packed i-rows: x,y,z,w1bits
    __shared__ int    s_iw2[ITERS];       // packed i-rows: w2

    const int t     = threadIdx.x;
    const int jbase = blockIdx.x * JTILE;
    const int i0    = blockIdx.y * ITERS;
    const int j0    = jbase + t * 4;

    // ---- pack the block's 16 i-rows into SMEM (once) ----
    if (t < ITERS) {
        const int i = i0 + t;
        const float x = xyz[(size_t)i * 3 + 0];
        const float y = xyz[(size_t)i * 3 + 1];
        const float z = xyz[(size_t)i * 3 + 2];
        const int b  = grid[(size_t)i * 5 + 0];
        const int bl = grid[(size_t)i * 5 + 1];
        const int c0 = grid[(size_t)i * 5 + 2];
        const int c1 = grid[(size_t)i * 5 + 3];
        const int c2 = grid[(size_t)i * 5 + 4];
        const int cx = (int)ceilf(__fdiv_rn(x, 3.0f));
        const int cy = (int)ceilf(__fdiv_rn(y, 3.0f));
        s_ipt[t] = make_float4(x, y, z,
                               __int_as_float((bl << 24) | (c2 << 16) | (c1 << 8) | c0));
        s_iw2[t] = (b << 16) | (cy << 8) | cx;
    }

    // ---- pack this thread's 4 j-points into registers (once) ----
    float qjx[4], qjy[4], qjz[4];
    int w1j[4], w2j[4], blj[4];
#pragma unroll
    for (int p = 0; p < 4; p++) {
        const int j = j0 + p;
        qjx[p] = __ldg(xyz + (size_t)j * 3 + 0);
        qjy[p] = __ldg(xyz + (size_t)j * 3 + 1);
        qjz[p] = __ldg(xyz + (size_t)j * 3 + 2);
        const int b  = __ldg(grid + (size_t)j * 5 + 0);
        const int bl = __ldg(grid + (size_t)j * 5 + 1);
        const int c0 = __ldg(grid + (size_t)j * 5 + 2);
        const int c1 = __ldg(grid + (size_t)j * 5 + 3);
        const int c2 = __ldg(grid + (size_t)j * 5 + 4);
        const int cx = (int)ceilf(__fdiv_rn(qjx[p], 3.0f));
        const int cy = (int)ceilf(__fdiv_rn(qjy[p], 3.0f));
        w1j[p] = (bl << 24) | (c2 << 16) | (c1 << 8) | c0;
        w2j[p] = (b << 16) | (cy << 8) | cx;
        blj[p] = bl;
    }

    __syncthreads();

    const size_t NN = (size_t)N * (size_t)N;

    for (int k = 0; k < ITERS; k++) {
        const int i = i0 + k;
        float* sb = sbuf[k & 1];

        // ---- per-i data: LDS broadcast ----
        const float4 qi  = s_ipt[k];
        const int    w1i = __float_as_int(qi.w);
        const int    w2i = s_iw2[k];
        const int    bli = ((unsigned)w1i) >> 24;
        const int    sci = bli >> 1;

        float dxv[12];
        float bkt[4], dsc[4], msk[4];

#pragma unroll
        for (int p = 0; p < 4; p++) {
            const float dx = qi.x - qjx[p];
            const float dy = qi.y - qjy[p];
            const float dz = qi.z - qjz[p];

            const unsigned d1 = __vabsdiffu4(w1i, w1j[p]);  // [c0d,c1d,c2d,bld]
            const unsigned d2 = __vabsdiffu4(w2i, w2j[p]);  // [cxd,cyd,bd,0]

            bool m = ((d2 & 0x00FF0000u) == 0u) && (bli <= blj[p]);
            if (m) {
                const bool fk = (d1 & 0xFFFEFEFEu) == 0u;
                if (!fk) {
                    const bool kc = (d2 & 0x0000FEFEu) == 0u;
                    const float r2 = __fadd_rn(__fadd_rn(__fmul_rn(dx, dx),
                                                         __fmul_rn(dy, dy)),
                                               __fmul_rn(dz, dz));
                    m = kc && (r2 <= 9.0f);
                }
            }

            if (m) {
                dxv[p * 3 + 0] = dx;
                dxv[p * 3 + 1] = dy;
                dxv[p * 3 + 2] = dz;
                bkt[p] = __fadd_rn(__fadd_rn(__fmul_rn(289.0f, bucket_base(dx)),
                                             __fmul_rn(17.0f, bucket_base(dy))),
                                   bucket_base(dz));
                dsc[p] = (float)((blj[p] >> 1) - sci);
                msk[p] = 1.0f;
            } else {
                dxv[p * 3 + 0] = 0.0f; dxv[p * 3 + 1] = 0.0f; dxv[p * 3 + 2] = 0.0f;
                bkt[p] = 0.0f; dsc[p] = 0.0f; msk[p] = 0.0f;
            }
        }

        // ---- ensure TMA from iter k-2 has finished READING this buffer ----
        if (t == 0 && k >= 2) {
            asm volatile("cp.async.bulk.wait_group.read 1;" ::: "memory");
        }
        __syncthreads();

        // ---- stage to SMEM (layout mirrors the global slices) ----
        float4* sdx = reinterpret_cast<float4*>(&sb[t * 12]);
        sdx[0] = make_float4(dxv[0], dxv[1], dxv[2],  dxv[3]);
        sdx[1] = make_float4(dxv[4], dxv[5], dxv[6],  dxv[7]);
        sdx[2] = make_float4(dxv[8], dxv[9], dxv[10], dxv[11]);
        *reinterpret_cast<float4*>(&sb[3 * JTILE + t * 4]) =
            make_float4(bkt[0], bkt[1], bkt[2], bkt[3]);
        *reinterpret_cast<float4*>(&sb[4 * JTILE + t * 4]) =
            make_float4(dsc[0], dsc[1], dsc[2], dsc[3]);
        *reinterpret_cast<float4*>(&sb[5 * JTILE + t * 4]) =
            make_float4(msk[0], msk[1], msk[2], msk[3]);

        __syncthreads();

        // ---- issue bulk async drain of this tile (overlaps next iteration) ----
        if (t == 0) {
            asm volatile("fence.proxy.async.shared::cta;" ::: "memory");

            const size_t row = (size_t)i * N + (size_t)jbase;
            float* g_dx = out + row * 3;
            float* g_bk = out + 3 * NN + row;
            float* g_ds = out + 4 * NN + row;
            float* g_mk = out + 5 * NN + row;

            const unsigned bytes1 = JTILE * 4u;
            const unsigned bytes3 = bytes1 * 3u;

            asm volatile("cp.async.bulk.global.shared::cta.bulk_group [%0], [%1], %2;"
                         :: "l"(g_dx), "r"(smem_u32(&sb[0])), "r"(bytes3) : "memory");
            asm volatile("cp.async.bulk.global.shared::cta.bulk_group [%0], [%1], %2;"
                         :: "l"(g_bk), "r"(smem_u32(&sb[3 * JTILE])), "r"(bytes1) : "memory");
            asm volatile("cp.async.bulk.global.shared::cta.bulk_group [%0], [%1], %2;"
                         :: "l"(g_ds), "r"(smem_u32(&sb[4 * JTILE])), "r"(bytes1) : "memory");
            asm volatile("cp.async.bulk.global.shared::cta.bulk_group [%0], [%1], %2;"
                         :: "l"(g_mk), "r"(smem_u32(&sb[5 * JTILE])), "r"(bytes1) : "memory");
            asm volatile("cp.async.bulk.commit_group;" ::: "memory");
        }
    }

    // ---- drain everything before SMEM is deallocated (block exit) ----
    if (t == 0) {
        asm volatile("cp.async.bulk.wait_group 0;" ::: "memory");
    }
    __syncthreads();
}

extern "C" void kernel_launch(void* const* d_in, const int* in_sizes, int n_in,
                              void* d_out, int out_size) {
    const float* xyz  = (const float*)d_in[0];   // [N,3] f32
    const int*   grid = (const int*)d_in[1];     // [N,5] i32
    float* out = (float*)d_out;

    const int N = in_sizes[0] / 3;               // 3072

    dim3 block(256, 1, 1);
    dim3 gridDim(N / JTILE, N / ITERS, 1);
    pair_kernel<<<gridDim, block>>>(xyz, grid, out, N);
}